// round 4
// baseline (speedup 1.0000x reference)
#include <cuda_runtime.h>
#include <cstdint>

#define NN 100000
#define D 128
#define CAP 192          // per-node in-edge bucket capacity (Poisson(16): P(deg>192) ~ 0)
#define BN_EPS 1e-5f

// Static device scratch (no allocations allowed)
__device__ float g_h[(size_t)NN * D];          // x @ W
__device__ float g_dinv[NN];                   // rsqrt(deg), deg = in-edges + 1 (self loop)
__device__ int   g_cnt[NN];                    // in-edge count
__device__ int   g_bucket[(size_t)NN * CAP];   // src node ids grouped by dst
__device__ int   g_is64;                       // 1 if edge_index is int64, 0 if int32

// ---------------------------------------------------------------------------
// GEMM: h = x @ W.  x:[n,128], W:[128,128], both row-major.
// Block tile 128x128, K-step 32. Static smem ~33KB. 256 threads, 8x8 microtile.
// ---------------------------------------------------------------------------
__global__ void gemm_kernel(const float* __restrict__ x,
                            const float* __restrict__ W,
                            int n) {
    __shared__ float As[128][33];   // [m][k] padded
    __shared__ float Bs[32][128];   // [k][n]

    int tid = threadIdx.x;
    int block_row = blockIdx.x * 128;

    int ty = tid >> 4;          // 0..15
    int tx = tid & 15;          // 0..15
    int row0 = ty * 8;
    int col0 = tx * 8;

    float acc[8][8];
    #pragma unroll
    for (int i = 0; i < 8; i++)
        #pragma unroll
        for (int j = 0; j < 8; j++) acc[i][j] = 0.f;

    for (int kk = 0; kk < 128; kk += 32) {
        // Load A tile: x[block_row .. +127][kk .. kk+31]
        #pragma unroll
        for (int i = tid; i < 1024; i += 256) {
            int r = i >> 3;
            int c4 = i & 7;
            int gr = block_row + r;
            float4 v = make_float4(0.f, 0.f, 0.f, 0.f);
            if (gr < n) v = ((const float4*)x)[(size_t)gr * 32 + (kk >> 2) + c4];
            As[r][c4 * 4 + 0] = v.x;
            As[r][c4 * 4 + 1] = v.y;
            As[r][c4 * 4 + 2] = v.z;
            As[r][c4 * 4 + 3] = v.w;
        }
        // Load B tile: W[kk .. kk+31][0..127]
        #pragma unroll
        for (int i = tid; i < 1024; i += 256) {
            int r = i >> 5;
            int c4 = i & 31;
            float4 v = ((const float4*)W)[(size_t)(kk + r) * 32 + c4];
            *(float4*)&Bs[r][c4 * 4] = v;
        }
        __syncthreads();

        #pragma unroll
        for (int k = 0; k < 32; k++) {
            float a[8], b[8];
            #pragma unroll
            for (int i = 0; i < 8; i++) a[i] = As[row0 + i][k];
            float4 b0 = *(const float4*)&Bs[k][col0];
            float4 b1 = *(const float4*)&Bs[k][col0 + 4];
            b[0] = b0.x; b[1] = b0.y; b[2] = b0.z; b[3] = b0.w;
            b[4] = b1.x; b[5] = b1.y; b[6] = b1.z; b[7] = b1.w;
            #pragma unroll
            for (int i = 0; i < 8; i++)
                #pragma unroll
                for (int j = 0; j < 8; j++)
                    acc[i][j] += a[i] * b[j];
        }
        __syncthreads();
    }

    #pragma unroll
    for (int i = 0; i < 8; i++) {
        int gr = block_row + row0 + i;
        if (gr < n) {
            float4* out4 = (float4*)&g_h[(size_t)gr * D + col0];
            out4[0] = make_float4(acc[i][0], acc[i][1], acc[i][2], acc[i][3]);
            out4[1] = make_float4(acc[i][4], acc[i][5], acc[i][6], acc[i][7]);
        }
    }
}

// ---------------------------------------------------------------------------
__global__ void zero_cnt_kernel(int n) {
    int i = blockIdx.x * blockDim.x + threadIdx.x;
    if (i < n) g_cnt[i] = 0;
    if (i == 0) g_is64 = 1;   // assume int64 until a nonzero "high word" is seen
}

// Detect edge_index dtype. Interpreting the buffer as int32 pairs:
// if true dtype is int64 (LE, values < 2^31), every odd int32 is 0.
// If true dtype is int32, odd positions hold edge ids (almost surely nonzero).
__global__ void detect_kernel(const int* __restrict__ ei32, int nprobe) {
    int i = blockIdx.x * blockDim.x + threadIdx.x;
    if (i < nprobe) {
        if (ei32[2 * i + 1] != 0) g_is64 = 0;
    }
}

// Bucket fill: for each edge, append src to dst's bucket.
__global__ void fill_kernel(const int* __restrict__ ei32, int E, int n) {
    int e = blockIdx.x * blockDim.x + threadIdx.x;
    if (e >= E) return;
    int src, dst;
    if (g_is64) {
        src = ei32[2 * (size_t)e];             // low word of int64
        dst = ei32[2 * ((size_t)E + e)];
    } else {
        src = ei32[e];
        dst = ei32[(size_t)E + e];
    }
    if ((unsigned)src >= (unsigned)n) return;  // trap-safety
    if ((unsigned)dst >= (unsigned)n) return;
    int slot = atomicAdd(&g_cnt[dst], 1);
    if (slot < CAP) g_bucket[(size_t)dst * CAP + slot] = src;
}

// dinv = rsqrt(in_deg + 1)   (self loop)
__global__ void dinv_kernel(int n) {
    int i = blockIdx.x * blockDim.x + threadIdx.x;
    if (i < n) {
        int c = g_cnt[i];
        g_dinv[i] = rsqrtf((float)(c + 1));
    }
}

// ---------------------------------------------------------------------------
// Gather + epilogue: one warp per node.
// agg = sum_{src in bucket[v]} h[src]*dinv[src]*dinv[v] + h[v]*dinv[v]^2
// out = relu((agg + b - rm) * rsqrt(rv+eps) * gamma + beta) + x
// ---------------------------------------------------------------------------
__global__ void gather_kernel(const float* __restrict__ x,
                              const float* __restrict__ b,
                              const float* __restrict__ gamma,
                              const float* __restrict__ beta,
                              const float* __restrict__ rm,
                              const float* __restrict__ rv,
                              float* __restrict__ out,
                              int n) {
    int w = (blockIdx.x * blockDim.x + threadIdx.x) >> 5;   // node id
    int lane = threadIdx.x & 31;
    if (w >= n) return;

    float dv = g_dinv[w];
    int cnt = g_cnt[w];
    if (cnt > CAP) cnt = CAP;

    const float4* h4 = (const float4*)g_h;

    // self-loop term
    float sn = dv * dv;
    float4 hv = h4[(size_t)w * 32 + lane];
    float ax = hv.x * sn, ay = hv.y * sn, az = hv.z * sn, aw = hv.w * sn;

    const int* bucket = &g_bucket[(size_t)w * CAP];
    int src_next = (cnt > 0) ? bucket[0] : 0;
    for (int j = 0; j < cnt; j++) {
        int src = src_next;
        if (j + 1 < cnt) src_next = bucket[j + 1];
        float norm = g_dinv[src] * dv;
        float4 t = h4[(size_t)src * 32 + lane];
        ax += t.x * norm;
        ay += t.y * norm;
        az += t.z * norm;
        aw += t.w * norm;
    }

    // epilogue
    float4 bb = ((const float4*)b)[lane];
    float4 m4 = ((const float4*)rm)[lane];
    float4 v4 = ((const float4*)rv)[lane];
    float4 g4 = ((const float4*)gamma)[lane];
    float4 e4 = ((const float4*)beta)[lane];
    float4 xv = ((const float4*)x)[(size_t)w * 32 + lane];

    float4 o;
    o.x = fmaxf((ax + bb.x - m4.x) * (g4.x * rsqrtf(v4.x + BN_EPS)) + e4.x, 0.f) + xv.x;
    o.y = fmaxf((ay + bb.y - m4.y) * (g4.y * rsqrtf(v4.y + BN_EPS)) + e4.y, 0.f) + xv.y;
    o.z = fmaxf((az + bb.z - m4.z) * (g4.z * rsqrtf(v4.z + BN_EPS)) + e4.z, 0.f) + xv.z;
    o.w = fmaxf((aw + bb.w - m4.w) * (g4.w * rsqrtf(v4.w + BN_EPS)) + e4.w, 0.f) + xv.w;
    ((float4*)out)[(size_t)w * 32 + lane] = o;
}

// ---------------------------------------------------------------------------
extern "C" void kernel_launch(void* const* d_in, const int* in_sizes, int n_in,
                              void* d_out, int out_size) {
    const float* x      = (const float*)d_in[0];
    const int* ei32     = (const int*)d_in[1];     // edge_index, int32 (or int64 -> detected)
    const float* W      = (const float*)d_in[2];
    const float* b      = (const float*)d_in[3];
    const float* gamma  = (const float*)d_in[4];
    const float* beta   = (const float*)d_in[5];
    const float* rm     = (const float*)d_in[6];
    const float* rv     = (const float*)d_in[7];
    float* out          = (float*)d_out;

    int n = in_sizes[0] / D;     // 100000
    int E = in_sizes[1] / 2;     // 1600000

    gemm_kernel<<<(n + 127) / 128, 256>>>(x, W, n);
    zero_cnt_kernel<<<(n + 255) / 256, 256>>>(n);
    int nprobe = (E < 1024) ? E : 1024;
    detect_kernel<<<(nprobe + 255) / 256, 256>>>(ei32, nprobe);
    fill_kernel<<<(E + 255) / 256, 256>>>(ei32, E, n);
    dinv_kernel<<<(n + 255) / 256, 256>>>(n);
    gather_kernel<<<(n * 32 + 255) / 256, 256>>>(x, b, gamma, beta, rm, rv, out, n);
}

// round 6
// speedup vs baseline: 1.1365x; 1.1365x over previous
#include <cuda_runtime.h>
#include <cuda_fp16.h>
#include <cstdint>

#define NN 100000
#define D 128
#define CAP 192          // per-node in-edge bucket capacity (Poisson(16): P(deg>192) ~ 0)
#define BN_EPS 1e-5f

// Static device scratch (no allocations allowed)
__device__ __half2 g_h2[(size_t)NN * 64];      // (x @ W) * dinv[row], fp16-compressed
__device__ float g_dinv[NN];                   // rsqrt(deg), deg = in-edges + 1 (self loop)
__device__ int   g_cnt[NN];                    // in-edge count
__device__ int   g_bucket[(size_t)NN * CAP];   // src node ids grouped by dst
__device__ int   g_is64 = 1;                   // 1 if edge_index is int64, 0 if int32 (monotone-cleared)

// ---------------------------------------------------------------------------
// Setup: zero counts + detect edge_index dtype.
// Interpreting the buffer as int32 pairs: if true dtype is int64 (LE, values
// < 2^31) every odd int32 is 0; if int32, odd slots hold ids (~never all 0).
// g_is64 is statically 1 and only ever cleared -> race-free and deterministic.
// ---------------------------------------------------------------------------
__global__ void setup_kernel(const int* __restrict__ ei32, int n, int nprobe) {
    int i = blockIdx.x * blockDim.x + threadIdx.x;
    if (i < n) g_cnt[i] = 0;
    if (i < nprobe) {
        if (ei32[2 * i + 1] != 0) g_is64 = 0;
    }
}

// Bucket fill: for each edge, append src to dst's bucket.
__global__ void fill_kernel(const int* __restrict__ ei32, int E, int n) {
    int e = blockIdx.x * blockDim.x + threadIdx.x;
    if (e >= E) return;
    int src, dst;
    if (g_is64) {
        src = ei32[2 * (size_t)e];             // low word of int64
        dst = ei32[2 * ((size_t)E + e)];
    } else {
        src = ei32[e];
        dst = ei32[(size_t)E + e];
    }
    if ((unsigned)src >= (unsigned)n) return;  // trap-safety
    if ((unsigned)dst >= (unsigned)n) return;
    int slot = atomicAdd(&g_cnt[dst], 1);
    if (slot < CAP) g_bucket[(size_t)dst * CAP + slot] = src;
}

// dinv = rsqrt(in_deg + 1)   (self loop)
__global__ void dinv_kernel(int n) {
    int i = blockIdx.x * blockDim.x + threadIdx.x;
    if (i < n) {
        int c = g_cnt[i];
        g_dinv[i] = rsqrtf((float)(c + 1));
    }
}

// ---------------------------------------------------------------------------
// GEMM: h_s = (x @ W) * dinv[row], output fp16.
// Block tile 128x128, K-step 32. 256 threads, 8x8 microtile.
// ---------------------------------------------------------------------------
__global__ void gemm_kernel(const float* __restrict__ x,
                            const float* __restrict__ W,
                            int n) {
    __shared__ float As[128][33];   // [m][k] padded
    __shared__ float Bs[32][128];   // [k][n]

    int tid = threadIdx.x;
    int block_row = blockIdx.x * 128;

    int ty = tid >> 4;          // 0..15
    int tx = tid & 15;          // 0..15
    int row0 = ty * 8;
    int col0 = tx * 8;

    float acc[8][8];
    #pragma unroll
    for (int i = 0; i < 8; i++)
        #pragma unroll
        for (int j = 0; j < 8; j++) acc[i][j] = 0.f;

    for (int kk = 0; kk < 128; kk += 32) {
        #pragma unroll
        for (int i = tid; i < 1024; i += 256) {
            int r = i >> 3;
            int c4 = i & 7;
            int gr = block_row + r;
            float4 v = make_float4(0.f, 0.f, 0.f, 0.f);
            if (gr < n) v = ((const float4*)x)[(size_t)gr * 32 + (kk >> 2) + c4];
            As[r][c4 * 4 + 0] = v.x;
            As[r][c4 * 4 + 1] = v.y;
            As[r][c4 * 4 + 2] = v.z;
            As[r][c4 * 4 + 3] = v.w;
        }
        #pragma unroll
        for (int i = tid; i < 1024; i += 256) {
            int r = i >> 5;
            int c4 = i & 31;
            float4 v = ((const float4*)W)[(size_t)(kk + r) * 32 + c4];
            *(float4*)&Bs[r][c4 * 4] = v;
        }
        __syncthreads();

        #pragma unroll
        for (int k = 0; k < 32; k++) {
            float a[8], b[8];
            #pragma unroll
            for (int i = 0; i < 8; i++) a[i] = As[row0 + i][k];
            float4 b0 = *(const float4*)&Bs[k][col0];
            float4 b1 = *(const float4*)&Bs[k][col0 + 4];
            b[0] = b0.x; b[1] = b0.y; b[2] = b0.z; b[3] = b0.w;
            b[4] = b1.x; b[5] = b1.y; b[6] = b1.z; b[7] = b1.w;
            #pragma unroll
            for (int i = 0; i < 8; i++)
                #pragma unroll
                for (int j = 0; j < 8; j++)
                    acc[i][j] += a[i] * b[j];
        }
        __syncthreads();
    }

    #pragma unroll
    for (int i = 0; i < 8; i++) {
        int gr = block_row + row0 + i;
        if (gr < n) {
            float di = g_dinv[gr];
            __half2 p[4];
            #pragma unroll
            for (int j = 0; j < 4; j++)
                p[j] = __floats2half2_rn(acc[i][2 * j] * di, acc[i][2 * j + 1] * di);
            __half2* dstp = &g_h2[(size_t)gr * 64 + (col0 >> 1)];
            *(uint2*)(dstp)     = *(uint2*)&p[0];
            *(uint2*)(dstp + 2) = *(uint2*)&p[2];
        }
    }
}

// ---------------------------------------------------------------------------
// Gather + epilogue: one warp per node, lane handles 4 features (2 half2).
// agg = dinv[v] * (h_s[v] + sum_{src in bucket[v]} h_s[src])
// out = relu((agg + b - rm) * rsqrt(rv+eps) * gamma + beta) + x
// ---------------------------------------------------------------------------
__global__ void gather_kernel(const float* __restrict__ x,
                              const float* __restrict__ b,
                              const float* __restrict__ gamma,
                              const float* __restrict__ beta,
                              const float* __restrict__ rm,
                              const float* __restrict__ rv,
                              float* __restrict__ out,
                              int n) {
    int w = (blockIdx.x * blockDim.x + threadIdx.x) >> 5;   // node id
    int lane = threadIdx.x & 31;
    if (w >= n) return;

    float dv = g_dinv[w];
    int cnt = g_cnt[w];
    if (cnt > CAP) cnt = CAP;

    // self term: h_s[w] (already includes dinv[w])
    uint2 raw = *(const uint2*)&g_h2[(size_t)w * 64 + lane * 2];
    float2 f0 = __half22float2(*(const __half2*)&raw.x);
    float2 f1 = __half22float2(*(const __half2*)&raw.y);
    float ax = f0.x, ay = f0.y, az = f1.x, aw = f1.y;

    const int* bucket = &g_bucket[(size_t)w * CAP];
    int src_next = (cnt > 0) ? bucket[0] : 0;
    for (int j = 0; j < cnt; j++) {
        int src = src_next;
        if (j + 1 < cnt) src_next = bucket[j + 1];
        uint2 t = *(const uint2*)&g_h2[(size_t)src * 64 + lane * 2];
        float2 t0 = __half22float2(*(const __half2*)&t.x);
        float2 t1 = __half22float2(*(const __half2*)&t.y);
        ax += t0.x; ay += t0.y; az += t1.x; aw += t1.y;
    }
    ax *= dv; ay *= dv; az *= dv; aw *= dv;

    // epilogue
    float4 bb = ((const float4*)b)[lane];
    float4 m4 = ((const float4*)rm)[lane];
    float4 v4 = ((const float4*)rv)[lane];
    float4 g4 = ((const float4*)gamma)[lane];
    float4 e4 = ((const float4*)beta)[lane];
    float4 xv = ((const float4*)x)[(size_t)w * 32 + lane];

    float4 o;
    o.x = fmaxf((ax + bb.x - m4.x) * (g4.x * rsqrtf(v4.x + BN_EPS)) + e4.x, 0.f) + xv.x;
    o.y = fmaxf((ay + bb.y - m4.y) * (g4.y * rsqrtf(v4.y + BN_EPS)) + e4.y, 0.f) + xv.y;
    o.z = fmaxf((az + bb.z - m4.z) * (g4.z * rsqrtf(v4.z + BN_EPS)) + e4.z, 0.f) + xv.z;
    o.w = fmaxf((aw + bb.w - m4.w) * (g4.w * rsqrtf(v4.w + BN_EPS)) + e4.w, 0.f) + xv.w;
    ((float4*)out)[(size_t)w * 32 + lane] = o;
}

// ---------------------------------------------------------------------------
extern "C" void kernel_launch(void* const* d_in, const int* in_sizes, int n_in,
                              void* d_out, int out_size) {
    const float* x      = (const float*)d_in[0];
    const int* ei32     = (const int*)d_in[1];     // edge_index (int32; int64 auto-detected)
    const float* W      = (const float*)d_in[2];
    const float* b      = (const float*)d_in[3];
    const float* gamma  = (const float*)d_in[4];
    const float* beta   = (const float*)d_in[5];
    const float* rm     = (const float*)d_in[6];
    const float* rv     = (const float*)d_in[7];
    float* out          = (float*)d_out;

    int n = in_sizes[0] / D;     // 100000
    int E = in_sizes[1] / 2;     // 1600000

    int nprobe = (E < 1024) ? E : 1024;
    setup_kernel<<<(n + 255) / 256, 256>>>(ei32, n, nprobe);
    fill_kernel<<<(E + 255) / 256, 256>>>(ei32, E, n);
    dinv_kernel<<<(n + 255) / 256, 256>>>(n);
    gemm_kernel<<<(n + 127) / 128, 256>>>(x, W, n);
    gather_kernel<<<(n * 32 + 255) / 256, 256>>>(x, b, gamma, beta, rm, rv, out, n);
}

// round 7
// speedup vs baseline: 1.6622x; 1.4625x over previous
#include <cuda_runtime.h>
#include <cuda_fp16.h>
#include <cstdint>

#define NN 100000
#define D 128
#define CAP 192          // per-node in-edge bucket capacity (Poisson(16): P(deg>192) ~ 0)
#define BN_EPS 1e-5f

// Static device scratch (no allocations allowed)
__device__ __half2 g_h2[(size_t)NN * 64];      // (x @ W) * dinv[row], fp16-compressed
__device__ float g_dinv[NN];                   // rsqrt(deg), deg = in-edges + 1 (self loop)
__device__ int   g_cnt[NN];                    // in-edge count
__device__ int   g_bucket[(size_t)NN * CAP];   // src node ids grouped by dst
__device__ int   g_is64 = 1;                   // 1 if edge_index is int64, 0 if int32

// ---------------------------------------------------------------------------
// Setup: zero counts + detect edge_index dtype (int64 vs int32, see R2 notes).
// ---------------------------------------------------------------------------
__global__ void setup_kernel(const int* __restrict__ ei32, int n, int nprobe) {
    int i = blockIdx.x * blockDim.x + threadIdx.x;
    if (i < n) g_cnt[i] = 0;
    if (i < nprobe) {
        if (ei32[2 * i + 1] != 0) g_is64 = 0;
    }
}

// Bucket fill: for each edge, append src to dst's bucket.
__global__ void fill_kernel(const int* __restrict__ ei32, int E, int n) {
    int e = blockIdx.x * blockDim.x + threadIdx.x;
    if (e >= E) return;
    int src, dst;
    if (g_is64) {
        src = ei32[2 * (size_t)e];
        dst = ei32[2 * ((size_t)E + e)];
    } else {
        src = ei32[e];
        dst = ei32[(size_t)E + e];
    }
    if ((unsigned)src >= (unsigned)n) return;  // trap-safety
    if ((unsigned)dst >= (unsigned)n) return;
    int slot = atomicAdd(&g_cnt[dst], 1);
    if (slot < CAP) g_bucket[(size_t)dst * CAP + slot] = src;
}

// dinv = rsqrt(in_deg + 1)   (self loop)
__global__ void dinv_kernel(int n) {
    int i = blockIdx.x * blockDim.x + threadIdx.x;
    if (i < n) {
        int c = g_cnt[i];
        g_dinv[i] = rsqrtf((float)(c + 1));
    }
}

// ---------------------------------------------------------------------------
// tf32 tensor-core GEMM: h_s = (x @ W) * dinv[row], output fp16.
// Block tile 128(M) x 128(N), K chunk 32, 256 threads = 8 warps.
// Warp tile 32x64 = 2(M) x 8(N) mma.m16n8k8 tiles.
// As stride 36 / Bs stride 136 -> conflict-free fragment LDS.
// ---------------------------------------------------------------------------
__device__ __forceinline__ unsigned f2tf32(float f) {
    unsigned u;
    asm("cvt.rna.tf32.f32 %0, %1;" : "=r"(u) : "f"(f));
    return u;
}

__global__ void gemm_kernel(const float* __restrict__ x,
                            const float* __restrict__ W,
                            int n) {
    __shared__ unsigned As[128 * 36];   // [row][k] stride 36
    __shared__ unsigned Bs[32 * 136];   // [k][col] stride 136

    int tid = threadIdx.x;
    int block_row = blockIdx.x * 128;

    int warp = tid >> 5;
    int lane = tid & 31;
    int group = lane >> 2;      // 0..7
    int tig = lane & 3;         // 0..3
    int warpM = warp & 3;       // 0..3 -> 32-row slab
    int warpN = warp >> 2;      // 0..1 -> 64-col slab

    float acc[2][8][4];
    #pragma unroll
    for (int t = 0; t < 2; t++)
        #pragma unroll
        for (int u = 0; u < 8; u++)
            #pragma unroll
            for (int v = 0; v < 4; v++) acc[t][u][v] = 0.f;

    for (int kk = 0; kk < 128; kk += 32) {
        // Load A chunk: x[block_row..+127][kk..kk+31] -> As (cvt to tf32)
        #pragma unroll
        for (int i = tid; i < 1024; i += 256) {      // 1024 float4 loads
            int r = i >> 3;          // row 0..127
            int c4 = i & 7;          // float4 within 32-wide K
            int gr = block_row + r;
            float4 v = make_float4(0.f, 0.f, 0.f, 0.f);
            if (gr < n) v = ((const float4*)x)[(size_t)gr * 32 + (kk >> 2) + c4];
            unsigned* p = &As[r * 36 + c4 * 4];
            p[0] = f2tf32(v.x); p[1] = f2tf32(v.y);
            p[2] = f2tf32(v.z); p[3] = f2tf32(v.w);
        }
        // Load B chunk: W[kk..kk+31][0..127] -> Bs
        #pragma unroll
        for (int i = tid; i < 1024; i += 256) {
            int r = i >> 5;          // k row 0..31
            int c4 = i & 31;         // float4 col
            float4 v = ((const float4*)W)[(size_t)(kk + r) * 32 + c4];
            unsigned* p = &Bs[r * 136 + c4 * 4];
            p[0] = f2tf32(v.x); p[1] = f2tf32(v.y);
            p[2] = f2tf32(v.z); p[3] = f2tf32(v.w);
        }
        __syncthreads();

        #pragma unroll
        for (int ks = 0; ks < 32; ks += 8) {
            // A fragments for both M tiles
            unsigned a[2][4];
            #pragma unroll
            for (int t = 0; t < 2; t++) {
                int rb = warpM * 32 + t * 16;
                a[t][0] = As[(rb + group) * 36 + ks + tig];
                a[t][1] = As[(rb + group + 8) * 36 + ks + tig];
                a[t][2] = As[(rb + group) * 36 + ks + tig + 4];
                a[t][3] = As[(rb + group + 8) * 36 + ks + tig + 4];
            }
            #pragma unroll
            for (int u = 0; u < 8; u++) {
                int cb = warpN * 64 + u * 8;
                unsigned b0 = Bs[(ks + tig) * 136 + cb + group];
                unsigned b1 = Bs[(ks + tig + 4) * 136 + cb + group];
                #pragma unroll
                for (int t = 0; t < 2; t++) {
                    asm volatile(
                        "mma.sync.aligned.m16n8k8.row.col.f32.tf32.tf32.f32 "
                        "{%0,%1,%2,%3}, {%4,%5,%6,%7}, {%8,%9}, {%0,%1,%2,%3};"
                        : "+f"(acc[t][u][0]), "+f"(acc[t][u][1]),
                          "+f"(acc[t][u][2]), "+f"(acc[t][u][3])
                        : "r"(a[t][0]), "r"(a[t][1]), "r"(a[t][2]), "r"(a[t][3]),
                          "r"(b0), "r"(b1));
                }
            }
        }
        __syncthreads();
    }

    // Epilogue: scale by dinv[row], pack to fp16, store.
    // Thread owns cols (2*tig, 2*tig+1) -> exactly one half2 per (t,u,rowhalf).
    #pragma unroll
    for (int t = 0; t < 2; t++) {
        int r0 = block_row + warpM * 32 + t * 16 + group;
        int r1 = r0 + 8;
        float d0 = (r0 < n) ? g_dinv[r0] : 0.f;
        float d1 = (r1 < n) ? g_dinv[r1] : 0.f;
        #pragma unroll
        for (int u = 0; u < 8; u++) {
            int colh = (warpN * 64 + u * 8 + 2 * tig) >> 1;   // half2 index
            if (r0 < n)
                g_h2[(size_t)r0 * 64 + colh] =
                    __floats2half2_rn(acc[t][u][0] * d0, acc[t][u][1] * d0);
            if (r1 < n)
                g_h2[(size_t)r1 * 64 + colh] =
                    __floats2half2_rn(acc[t][u][2] * d1, acc[t][u][3] * d1);
        }
    }
}

// ---------------------------------------------------------------------------
// Gather + epilogue: one warp per node, lane handles 4 features (2 half2).
// agg = dinv[v] * (h_s[v] + sum_{src in bucket[v]} h_s[src])
// out = relu((agg + b - rm) * rsqrt(rv+eps) * gamma + beta) + x
// ---------------------------------------------------------------------------
__global__ void gather_kernel(const float* __restrict__ x,
                              const float* __restrict__ b,
                              const float* __restrict__ gamma,
                              const float* __restrict__ beta,
                              const float* __restrict__ rm,
                              const float* __restrict__ rv,
                              float* __restrict__ out,
                              int n) {
    int w = (blockIdx.x * blockDim.x + threadIdx.x) >> 5;   // node id
    int lane = threadIdx.x & 31;
    if (w >= n) return;

    float dv = g_dinv[w];
    int cnt = g_cnt[w];
    if (cnt > CAP) cnt = CAP;

    uint2 raw = *(const uint2*)&g_h2[(size_t)w * 64 + lane * 2];
    float2 f0 = __half22float2(*(const __half2*)&raw.x);
    float2 f1 = __half22float2(*(const __half2*)&raw.y);
    float ax = f0.x, ay = f0.y, az = f1.x, aw = f1.y;

    const int* bucket = &g_bucket[(size_t)w * CAP];
    int src_next = (cnt > 0) ? bucket[0] : 0;
    for (int j = 0; j < cnt; j++) {
        int src = src_next;
        if (j + 1 < cnt) src_next = bucket[j + 1];
        uint2 t = *(const uint2*)&g_h2[(size_t)src * 64 + lane * 2];
        float2 t0 = __half22float2(*(const __half2*)&t.x);
        float2 t1 = __half22float2(*(const __half2*)&t.y);
        ax += t0.x; ay += t0.y; az += t1.x; aw += t1.y;
    }
    ax *= dv; ay *= dv; az *= dv; aw *= dv;

    float4 bb = ((const float4*)b)[lane];
    float4 m4 = ((const float4*)rm)[lane];
    float4 v4 = ((const float4*)rv)[lane];
    float4 g4 = ((const float4*)gamma)[lane];
    float4 e4 = ((const float4*)beta)[lane];
    float4 xv = ((const float4*)x)[(size_t)w * 32 + lane];

    float4 o;
    o.x = fmaxf((ax + bb.x - m4.x) * (g4.x * rsqrtf(v4.x + BN_EPS)) + e4.x, 0.f) + xv.x;
    o.y = fmaxf((ay + bb.y - m4.y) * (g4.y * rsqrtf(v4.y + BN_EPS)) + e4.y, 0.f) + xv.y;
    o.z = fmaxf((az + bb.z - m4.z) * (g4.z * rsqrtf(v4.z + BN_EPS)) + e4.z, 0.f) + xv.z;
    o.w = fmaxf((aw + bb.w - m4.w) * (g4.w * rsqrtf(v4.w + BN_EPS)) + e4.w, 0.f) + xv.w;
    ((float4*)out)[(size_t)w * 32 + lane] = o;
}

// ---------------------------------------------------------------------------
extern "C" void kernel_launch(void* const* d_in, const int* in_sizes, int n_in,
                              void* d_out, int out_size) {
    const float* x      = (const float*)d_in[0];
    const int* ei32     = (const int*)d_in[1];     // edge_index (int32; int64 auto-detected)
    const float* W      = (const float*)d_in[2];
    const float* b      = (const float*)d_in[3];
    const float* gamma  = (const float*)d_in[4];
    const float* beta   = (const float*)d_in[5];
    const float* rm     = (const float*)d_in[6];
    const float* rv     = (const float*)d_in[7];
    float* out          = (float*)d_out;

    int n = in_sizes[0] / D;     // 100000
    int E = in_sizes[1] / 2;     // 1600000

    int nprobe = (E < 1024) ? E : 1024;
    setup_kernel<<<(n + 255) / 256, 256>>>(ei32, n, nprobe);
    fill_kernel<<<(E + 255) / 256, 256>>>(ei32, E, n);
    dinv_kernel<<<(n + 255) / 256, 256>>>(n);
    gemm_kernel<<<(n + 127) / 128, 256>>>(x, W, n);
    gather_kernel<<<(n * 32 + 255) / 256, 256>>>(x, b, gamma, beta, rm, rv, out, n);
}

// round 8
// speedup vs baseline: 1.9153x; 1.1523x over previous
#include <cuda_runtime.h>
#include <cuda_fp16.h>
#include <cstdint>

#define NN 100000
#define D 128
#define CAP 192          // per-node in-edge bucket capacity (Poisson(16): P(deg>192) ~ 0)
#define BN_EPS 1e-5f

// Static device scratch (no allocations allowed)
__device__ __half2 g_h2[(size_t)NN * 64];      // (x @ W) * dinv[row], fp16-compressed
__device__ int   g_cnt[NN];                    // in-edge count
__device__ int   g_bucket[(size_t)NN * CAP];   // src node ids grouped by dst
__device__ int   g_is64 = 1;                   // 1 if edge_index is int64, 0 if int32

// ---------------------------------------------------------------------------
// Setup: zero counts + detect edge_index dtype (int64 vs int32).
// ---------------------------------------------------------------------------
__global__ void setup_kernel(const int* __restrict__ ei32, int n, int nprobe) {
    int i = blockIdx.x * blockDim.x + threadIdx.x;
    if (i < n) g_cnt[i] = 0;
    if (i < nprobe) {
        if (ei32[2 * i + 1] != 0) g_is64 = 0;
    }
}

// ---------------------------------------------------------------------------
// Bucket fill: 4 edges per thread, vectorized int4 loads on the int32 path.
// ---------------------------------------------------------------------------
__global__ void fill_kernel(const int* __restrict__ ei32, int E, int n) {
    int t = blockIdx.x * blockDim.x + threadIdx.x;
    int e0 = t * 4;
    if (e0 >= E) return;

    int srcs[4], dsts[4];
    int m = (E - e0 < 4) ? (E - e0) : 4;

    if (!g_is64 && m == 4 && (E & 3) == 0) {
        int4 s4 = *(const int4*)&ei32[e0];
        int4 d4 = *(const int4*)&ei32[(size_t)E + e0];
        srcs[0] = s4.x; srcs[1] = s4.y; srcs[2] = s4.z; srcs[3] = s4.w;
        dsts[0] = d4.x; dsts[1] = d4.y; dsts[2] = d4.z; dsts[3] = d4.w;
    } else {
        #pragma unroll
        for (int j = 0; j < 4; j++) {
            if (j < m) {
                int e = e0 + j;
                if (g_is64) {
                    srcs[j] = ei32[2 * (size_t)e];
                    dsts[j] = ei32[2 * ((size_t)E + e)];
                } else {
                    srcs[j] = ei32[e];
                    dsts[j] = ei32[(size_t)E + e];
                }
            } else { srcs[j] = -1; dsts[j] = -1; }
        }
    }

    #pragma unroll
    for (int j = 0; j < 4; j++) {
        int src = srcs[j], dst = dsts[j];
        if ((unsigned)src >= (unsigned)n) continue;   // trap-safety
        if ((unsigned)dst >= (unsigned)n) continue;
        int slot = atomicAdd(&g_cnt[dst], 1);
        if (slot < CAP) g_bucket[(size_t)dst * CAP + slot] = src;
    }
}

// ---------------------------------------------------------------------------
// tf32 tensor-core GEMM with cp.async double buffering.
// h_s = (x @ W) * rsqrt(cnt+1), output fp16.
// Block tile 128x128, K chunk 32, 2 stages, 256 threads = 8 warps.
// As stride 36 / Bs stride 136 (fp32 in smem, cvt->tf32 at fragment load).
// ---------------------------------------------------------------------------
#define AS_WORDS (128 * 36)
#define BS_WORDS (32 * 136)
#define STAGE_WORDS (AS_WORDS + BS_WORDS)
#define GEMM_SMEM (2 * STAGE_WORDS * 4)

__device__ __forceinline__ unsigned f2tf32(float f) {
    unsigned u;
    asm("cvt.rna.tf32.f32 %0, %1;" : "=r"(u) : "f"(f));
    return u;
}

__device__ __forceinline__ void cp16(float* dst, const float* src) {
    unsigned d = (unsigned)__cvta_generic_to_shared(dst);
    asm volatile("cp.async.cg.shared.global [%0], [%1], 16;" :: "r"(d), "l"(src));
}

__global__ void __launch_bounds__(256) gemm_kernel(const float* __restrict__ x,
                                                   const float* __restrict__ W,
                                                   int n) {
    extern __shared__ float sm[];

    int tid = threadIdx.x;
    int block_row = blockIdx.x * 128;

    int warp = tid >> 5;
    int lane = tid & 31;
    int group = lane >> 2;      // 0..7
    int tig = lane & 3;         // 0..3
    int warpM = warp & 3;       // 0..3 -> 32-row slab
    int warpN = warp >> 2;      // 0..1 -> 64-col slab

    // Issue async loads of chunk kk into stage s
    auto load_chunk = [&](int s, int kk) {
        float* As = sm + s * STAGE_WORDS;
        float* Bs = As + AS_WORDS;
        #pragma unroll
        for (int i = tid; i < 1024; i += 256) {   // A: 128 rows x 8 float4
            int r = i >> 3;
            int c4 = i & 7;
            int gr = block_row + r;
            if (gr >= n) gr = n - 1;              // clamp; ragged rows discarded at store
            cp16(&As[r * 36 + c4 * 4], &x[(size_t)gr * 128 + kk + c4 * 4]);
        }
        #pragma unroll
        for (int i = tid; i < 1024; i += 256) {   // B: 32 k-rows x 32 float4
            int r = i >> 5;
            int c4 = i & 31;
            cp16(&Bs[r * 136 + c4 * 4], &W[(size_t)(kk + r) * 128 + c4 * 4]);
        }
        asm volatile("cp.async.commit_group;");
    };

    float acc[2][8][4];
    #pragma unroll
    for (int t = 0; t < 2; t++)
        #pragma unroll
        for (int u = 0; u < 8; u++)
            #pragma unroll
            for (int v = 0; v < 4; v++) acc[t][u][v] = 0.f;

    load_chunk(0, 0);

    #pragma unroll
    for (int c = 0; c < 4; c++) {
        if (c < 3) load_chunk((c + 1) & 1, (c + 1) * 32);

        if (c < 3) asm volatile("cp.async.wait_group 1;");
        else       asm volatile("cp.async.wait_group 0;");
        __syncthreads();

        const float* As = sm + (c & 1) * STAGE_WORDS;
        const float* Bs = As + AS_WORDS;

        #pragma unroll
        for (int ks = 0; ks < 32; ks += 8) {
            unsigned a[2][4];
            #pragma unroll
            for (int t = 0; t < 2; t++) {
                int rb = warpM * 32 + t * 16;
                a[t][0] = f2tf32(As[(rb + group) * 36 + ks + tig]);
                a[t][1] = f2tf32(As[(rb + group + 8) * 36 + ks + tig]);
                a[t][2] = f2tf32(As[(rb + group) * 36 + ks + tig + 4]);
                a[t][3] = f2tf32(As[(rb + group + 8) * 36 + ks + tig + 4]);
            }
            #pragma unroll
            for (int u = 0; u < 8; u++) {
                int cb = warpN * 64 + u * 8;
                unsigned b0 = f2tf32(Bs[(ks + tig) * 136 + cb + group]);
                unsigned b1 = f2tf32(Bs[(ks + tig + 4) * 136 + cb + group]);
                #pragma unroll
                for (int t = 0; t < 2; t++) {
                    asm volatile(
                        "mma.sync.aligned.m16n8k8.row.col.f32.tf32.tf32.f32 "
                        "{%0,%1,%2,%3}, {%4,%5,%6,%7}, {%8,%9}, {%0,%1,%2,%3};"
                        : "+f"(acc[t][u][0]), "+f"(acc[t][u][1]),
                          "+f"(acc[t][u][2]), "+f"(acc[t][u][3])
                        : "r"(a[t][0]), "r"(a[t][1]), "r"(a[t][2]), "r"(a[t][3]),
                          "r"(b0), "r"(b1));
                }
            }
        }
        __syncthreads();
    }

    // Epilogue: scale by rsqrt(cnt+1), pack fp16, store.
    #pragma unroll
    for (int t = 0; t < 2; t++) {
        int r0 = block_row + warpM * 32 + t * 16 + group;
        int r1 = r0 + 8;
        float d0 = (r0 < n) ? rsqrtf((float)(g_cnt[r0] + 1)) : 0.f;
        float d1 = (r1 < n) ? rsqrtf((float)(g_cnt[r1] + 1)) : 0.f;
        #pragma unroll
        for (int u = 0; u < 8; u++) {
            int colh = (warpN * 64 + u * 8 + 2 * tig) >> 1;
            if (r0 < n)
                g_h2[(size_t)r0 * 64 + colh] =
                    __floats2half2_rn(acc[t][u][0] * d0, acc[t][u][1] * d0);
            if (r1 < n)
                g_h2[(size_t)r1 * 64 + colh] =
                    __floats2half2_rn(acc[t][u][2] * d1, acc[t][u][3] * d1);
        }
    }
}

// ---------------------------------------------------------------------------
// Gather + epilogue: one warp per node, lane handles 4 features (2 half2).
// agg = dinv[v] * (h_s[v] + sum_{src in bucket[v]} h_s[src])
// out = relu((agg + b - rm) * rsqrt(rv+eps) * gamma + beta) + x
// ---------------------------------------------------------------------------
__global__ void gather_kernel(const float* __restrict__ x,
                              const float* __restrict__ b,
                              const float* __restrict__ gamma,
                              const float* __restrict__ beta,
                              const float* __restrict__ rm,
                              const float* __restrict__ rv,
                              float* __restrict__ out,
                              int n) {
    int w = (blockIdx.x * blockDim.x + threadIdx.x) >> 5;   // node id
    int lane = threadIdx.x & 31;
    if (w >= n) return;

    int full = g_cnt[w];
    float dv = rsqrtf((float)(full + 1));
    int cnt = (full > CAP) ? CAP : full;

    uint2 raw = *(const uint2*)&g_h2[(size_t)w * 64 + lane * 2];
    float2 f0 = __half22float2(*(const __half2*)&raw.x);
    float2 f1 = __half22float2(*(const __half2*)&raw.y);
    float ax = f0.x, ay = f0.y, az = f1.x, aw = f1.y;

    const int* bucket = &g_bucket[(size_t)w * CAP];
    int src_next = (cnt > 0) ? bucket[0] : 0;
    for (int j = 0; j < cnt; j++) {
        int src = src_next;
        if (j + 1 < cnt) src_next = bucket[j + 1];
        uint2 t = *(const uint2*)&g_h2[(size_t)src * 64 + lane * 2];
        float2 t0 = __half22float2(*(const __half2*)&t.x);
        float2 t1 = __half22float2(*(const __half2*)&t.y);
        ax += t0.x; ay += t0.y; az += t1.x; aw += t1.y;
    }
    ax *= dv; ay *= dv; az *= dv; aw *= dv;

    float4 bb = ((const float4*)b)[lane];
    float4 m4 = ((const float4*)rm)[lane];
    float4 v4 = ((const float4*)rv)[lane];
    float4 g4 = ((const float4*)gamma)[lane];
    float4 e4 = ((const float4*)beta)[lane];
    float4 xv = ((const float4*)x)[(size_t)w * 32 + lane];

    float4 o;
    o.x = fmaxf((ax + bb.x - m4.x) * (g4.x * rsqrtf(v4.x + BN_EPS)) + e4.x, 0.f) + xv.x;
    o.y = fmaxf((ay + bb.y - m4.y) * (g4.y * rsqrtf(v4.y + BN_EPS)) + e4.y, 0.f) + xv.y;
    o.z = fmaxf((az + bb.z - m4.z) * (g4.z * rsqrtf(v4.z + BN_EPS)) + e4.z, 0.f) + xv.z;
    o.w = fmaxf((aw + bb.w - m4.w) * (g4.w * rsqrtf(v4.w + BN_EPS)) + e4.w, 0.f) + xv.w;
    ((float4*)out)[(size_t)w * 32 + lane] = o;
}

// ---------------------------------------------------------------------------
extern "C" void kernel_launch(void* const* d_in, const int* in_sizes, int n_in,
                              void* d_out, int out_size) {
    const float* x      = (const float*)d_in[0];
    const int* ei32     = (const int*)d_in[1];     // edge_index (int32; int64 auto-detected)
    const float* W      = (const float*)d_in[2];
    const float* b      = (const float*)d_in[3];
    const float* gamma  = (const float*)d_in[4];
    const float* beta   = (const float*)d_in[5];
    const float* rm     = (const float*)d_in[6];
    const float* rv     = (const float*)d_in[7];
    float* out          = (float*)d_out;

    int n = in_sizes[0] / D;     // 100000
    int E = in_sizes[1] / 2;     // 1600000

    cudaFuncSetAttribute(gemm_kernel,
                         cudaFuncAttributeMaxDynamicSharedMemorySize, GEMM_SMEM);

    int nprobe = (E < 1024) ? E : 1024;
    setup_kernel<<<(n + 255) / 256, 256>>>(ei32, n, nprobe);
    fill_kernel<<<((E + 3) / 4 + 255) / 256, 256>>>(ei32, E, n);
    gemm_kernel<<<(n + 127) / 128, 256, GEMM_SMEM>>>(x, W, n);
    gather_kernel<<<(n * 32 + 255) / 256, 256>>>(x, b, gamma, beta, rm, rv, out, n);
}

// round 9
// speedup vs baseline: 1.9839x; 1.0358x over previous
#include <cuda_runtime.h>
#include <cuda_fp16.h>
#include <cstdint>

#define NN 100000
#define D 128
#define CAP 192          // per-node in-edge bucket capacity (Poisson(16): P(deg>192) ~ 0)
#define BN_EPS 1e-5f

// Static device scratch (no allocations allowed)
__device__ __half2 g_h2[(size_t)NN * 64];      // (x @ W) * dinv[row], fp16-compressed
__device__ int   g_cnt[NN];                    // in-edge count
__device__ int   g_bucket[(size_t)NN * CAP];   // src node ids grouped by dst
__device__ int   g_is64 = 1;                   // 1 if edge_index is int64, 0 if int32

// ---------------------------------------------------------------------------
// Setup: zero counts + detect edge_index dtype (int64 vs int32).
// ---------------------------------------------------------------------------
__global__ void setup_kernel(const int* __restrict__ ei32, int n, int nprobe) {
    int i = blockIdx.x * blockDim.x + threadIdx.x;
    if (i < n) g_cnt[i] = 0;
    if (i < nprobe) {
        if (ei32[2 * i + 1] != 0) g_is64 = 0;
    }
}

// ---------------------------------------------------------------------------
// Bucket fill: 4 edges per thread, vectorized int4 loads on the int32 path.
// ---------------------------------------------------------------------------
__global__ void fill_kernel(const int* __restrict__ ei32, int E, int n) {
    int t = blockIdx.x * blockDim.x + threadIdx.x;
    int e0 = t * 4;
    if (e0 >= E) return;

    int srcs[4], dsts[4];
    int m = (E - e0 < 4) ? (E - e0) : 4;

    if (!g_is64 && m == 4 && (E & 3) == 0) {
        int4 s4 = *(const int4*)&ei32[e0];
        int4 d4 = *(const int4*)&ei32[(size_t)E + e0];
        srcs[0] = s4.x; srcs[1] = s4.y; srcs[2] = s4.z; srcs[3] = s4.w;
        dsts[0] = d4.x; dsts[1] = d4.y; dsts[2] = d4.z; dsts[3] = d4.w;
    } else {
        #pragma unroll
        for (int j = 0; j < 4; j++) {
            if (j < m) {
                int e = e0 + j;
                if (g_is64) {
                    srcs[j] = ei32[2 * (size_t)e];
                    dsts[j] = ei32[2 * ((size_t)E + e)];
                } else {
                    srcs[j] = ei32[e];
                    dsts[j] = ei32[(size_t)E + e];
                }
            } else { srcs[j] = -1; dsts[j] = -1; }
        }
    }

    #pragma unroll
    for (int j = 0; j < 4; j++) {
        int src = srcs[j], dst = dsts[j];
        if ((unsigned)src >= (unsigned)n) continue;   // trap-safety
        if ((unsigned)dst >= (unsigned)n) continue;
        int slot = atomicAdd(&g_cnt[dst], 1);
        if (slot < CAP) g_bucket[(size_t)dst * CAP + slot] = src;
    }
}

// ---------------------------------------------------------------------------
// tf32 tensor-core GEMM with cp.async double buffering.
// h_s = (x @ W) * rsqrt(cnt+1), output fp16.
// ---------------------------------------------------------------------------
#define AS_WORDS (128 * 36)
#define BS_WORDS (32 * 136)
#define STAGE_WORDS (AS_WORDS + BS_WORDS)
#define GEMM_SMEM (2 * STAGE_WORDS * 4)

__device__ __forceinline__ unsigned f2tf32(float f) {
    unsigned u;
    asm("cvt.rna.tf32.f32 %0, %1;" : "=r"(u) : "f"(f));
    return u;
}

__device__ __forceinline__ void cp16(float* dst, const float* src) {
    unsigned d = (unsigned)__cvta_generic_to_shared(dst);
    asm volatile("cp.async.cg.shared.global [%0], [%1], 16;" :: "r"(d), "l"(src));
}

__global__ void __launch_bounds__(256) gemm_kernel(const float* __restrict__ x,
                                                   const float* __restrict__ W,
                                                   int n) {
    extern __shared__ float sm[];

    int tid = threadIdx.x;
    int block_row = blockIdx.x * 128;

    int warp = tid >> 5;
    int lane = tid & 31;
    int group = lane >> 2;      // 0..7
    int tig = lane & 3;         // 0..3
    int warpM = warp & 3;       // 0..3 -> 32-row slab
    int warpN = warp >> 2;      // 0..1 -> 64-col slab

    auto load_chunk = [&](int s, int kk) {
        float* As = sm + s * STAGE_WORDS;
        float* Bs = As + AS_WORDS;
        #pragma unroll
        for (int i = tid; i < 1024; i += 256) {   // A: 128 rows x 8 float4
            int r = i >> 3;
            int c4 = i & 7;
            int gr = block_row + r;
            if (gr >= n) gr = n - 1;              // clamp; ragged rows discarded at store
            cp16(&As[r * 36 + c4 * 4], &x[(size_t)gr * 128 + kk + c4 * 4]);
        }
        #pragma unroll
        for (int i = tid; i < 1024; i += 256) {   // B: 32 k-rows x 32 float4
            int r = i >> 5;
            int c4 = i & 31;
            cp16(&Bs[r * 136 + c4 * 4], &W[(size_t)(kk + r) * 128 + c4 * 4]);
        }
        asm volatile("cp.async.commit_group;");
    };

    float acc[2][8][4];
    #pragma unroll
    for (int t = 0; t < 2; t++)
        #pragma unroll
        for (int u = 0; u < 8; u++)
            #pragma unroll
            for (int v = 0; v < 4; v++) acc[t][u][v] = 0.f;

    load_chunk(0, 0);

    #pragma unroll
    for (int c = 0; c < 4; c++) {
        if (c < 3) load_chunk((c + 1) & 1, (c + 1) * 32);

        if (c < 3) asm volatile("cp.async.wait_group 1;");
        else       asm volatile("cp.async.wait_group 0;");
        __syncthreads();

        const float* As = sm + (c & 1) * STAGE_WORDS;
        const float* Bs = As + AS_WORDS;

        #pragma unroll
        for (int ks = 0; ks < 32; ks += 8) {
            unsigned a[2][4];
            #pragma unroll
            for (int t = 0; t < 2; t++) {
                int rb = warpM * 32 + t * 16;
                a[t][0] = f2tf32(As[(rb + group) * 36 + ks + tig]);
                a[t][1] = f2tf32(As[(rb + group + 8) * 36 + ks + tig]);
                a[t][2] = f2tf32(As[(rb + group) * 36 + ks + tig + 4]);
                a[t][3] = f2tf32(As[(rb + group + 8) * 36 + ks + tig + 4]);
            }
            #pragma unroll
            for (int u = 0; u < 8; u++) {
                int cb = warpN * 64 + u * 8;
                unsigned b0 = f2tf32(Bs[(ks + tig) * 136 + cb + group]);
                unsigned b1 = f2tf32(Bs[(ks + tig + 4) * 136 + cb + group]);
                #pragma unroll
                for (int t = 0; t < 2; t++) {
                    asm volatile(
                        "mma.sync.aligned.m16n8k8.row.col.f32.tf32.tf32.f32 "
                        "{%0,%1,%2,%3}, {%4,%5,%6,%7}, {%8,%9}, {%0,%1,%2,%3};"
                        : "+f"(acc[t][u][0]), "+f"(acc[t][u][1]),
                          "+f"(acc[t][u][2]), "+f"(acc[t][u][3])
                        : "r"(a[t][0]), "r"(a[t][1]), "r"(a[t][2]), "r"(a[t][3]),
                          "r"(b0), "r"(b1));
                }
            }
        }
        __syncthreads();
    }

    #pragma unroll
    for (int t = 0; t < 2; t++) {
        int r0 = block_row + warpM * 32 + t * 16 + group;
        int r1 = r0 + 8;
        float d0 = (r0 < n) ? rsqrtf((float)(g_cnt[r0] + 1)) : 0.f;
        float d1 = (r1 < n) ? rsqrtf((float)(g_cnt[r1] + 1)) : 0.f;
        #pragma unroll
        for (int u = 0; u < 8; u++) {
            int colh = (warpN * 64 + u * 8 + 2 * tig) >> 1;
            if (r0 < n)
                g_h2[(size_t)r0 * 64 + colh] =
                    __floats2half2_rn(acc[t][u][0] * d0, acc[t][u][1] * d0);
            if (r1 < n)
                g_h2[(size_t)r1 * 64 + colh] =
                    __floats2half2_rn(acc[t][u][2] * d1, acc[t][u][3] * d1);
        }
    }
}

// ---------------------------------------------------------------------------
// Gather + epilogue: one warp per node, lane handles 4 features (2 half2).
// Strip-mined by 4 edges: int4 bucket load, 4 h2 loads in flight (MLP=4),
// pairwise HADD2 tree, single cvt+FADD into fp32 accumulators per group.
// agg = dinv[v] * (h_s[v] + sum_src h_s[src]);  out = relu(BN(agg+b)) + x
// ---------------------------------------------------------------------------
__global__ void gather_kernel(const float* __restrict__ x,
                              const float* __restrict__ b,
                              const float* __restrict__ gamma,
                              const float* __restrict__ beta,
                              const float* __restrict__ rm,
                              const float* __restrict__ rv,
                              float* __restrict__ out,
                              int n) {
    int w = (blockIdx.x * blockDim.x + threadIdx.x) >> 5;   // node id
    int lane = threadIdx.x & 31;
    if (w >= n) return;

    int full = g_cnt[w];
    float dv = rsqrtf((float)(full + 1));
    int cnt = (full > CAP) ? CAP : full;

    const uint2* h2v = (const uint2*)g_h2;      // one uint2 = 4 features

    // self term
    uint2 raw = h2v[(size_t)w * 32 + lane];
    float2 f0 = __half22float2(*(const __half2*)&raw.x);
    float2 f1 = __half22float2(*(const __half2*)&raw.y);
    float ax = f0.x, ay = f0.y, az = f1.x, aw = f1.y;

    const int* bucket = &g_bucket[(size_t)w * CAP];

    int j = 0;
    for (; j + 4 <= cnt; j += 4) {
        int4 s4 = *(const int4*)&bucket[j];     // uniform 16B load
        uint2 t0 = h2v[(size_t)s4.x * 32 + lane];
        uint2 t1 = h2v[(size_t)s4.y * 32 + lane];
        uint2 t2 = h2v[(size_t)s4.z * 32 + lane];
        uint2 t3 = h2v[(size_t)s4.w * 32 + lane];

        // pairwise half2 tree (2 fp16-rounding levels)
        __half2 lo = __hadd2(__hadd2(*(const __half2*)&t0.x, *(const __half2*)&t1.x),
                             __hadd2(*(const __half2*)&t2.x, *(const __half2*)&t3.x));
        __half2 hi = __hadd2(__hadd2(*(const __half2*)&t0.y, *(const __half2*)&t1.y),
                             __hadd2(*(const __half2*)&t2.y, *(const __half2*)&t3.y));
        float2 lf = __half22float2(lo);
        float2 hf = __half22float2(hi);
        ax += lf.x; ay += lf.y; az += hf.x; aw += hf.y;
    }
    for (; j < cnt; j++) {
        int src = bucket[j];
        uint2 t = h2v[(size_t)src * 32 + lane];
        float2 t0 = __half22float2(*(const __half2*)&t.x);
        float2 t1 = __half22float2(*(const __half2*)&t.y);
        ax += t0.x; ay += t0.y; az += t1.x; aw += t1.y;
    }
    ax *= dv; ay *= dv; az *= dv; aw *= dv;

    // epilogue
    float4 bb = ((const float4*)b)[lane];
    float4 m4 = ((const float4*)rm)[lane];
    float4 v4 = ((const float4*)rv)[lane];
    float4 g4 = ((const float4*)gamma)[lane];
    float4 e4 = ((const float4*)beta)[lane];
    float4 xv = ((const float4*)x)[(size_t)w * 32 + lane];

    float4 o;
    o.x = fmaxf((ax + bb.x - m4.x) * (g4.x * rsqrtf(v4.x + BN_EPS)) + e4.x, 0.f) + xv.x;
    o.y = fmaxf((ay + bb.y - m4.y) * (g4.y * rsqrtf(v4.y + BN_EPS)) + e4.y, 0.f) + xv.y;
    o.z = fmaxf((az + bb.z - m4.z) * (g4.z * rsqrtf(v4.z + BN_EPS)) + e4.z, 0.f) + xv.z;
    o.w = fmaxf((aw + bb.w - m4.w) * (g4.w * rsqrtf(v4.w + BN_EPS)) + e4.w, 0.f) + xv.w;
    ((float4*)out)[(size_t)w * 32 + lane] = o;
}

// ---------------------------------------------------------------------------
extern "C" void kernel_launch(void* const* d_in, const int* in_sizes, int n_in,
                              void* d_out, int out_size) {
    const float* x      = (const float*)d_in[0];
    const int* ei32     = (const int*)d_in[1];     // edge_index (int32; int64 auto-detected)
    const float* W      = (const float*)d_in[2];
    const float* b      = (const float*)d_in[3];
    const float* gamma  = (const float*)d_in[4];
    const float* beta   = (const float*)d_in[5];
    const float* rm     = (const float*)d_in[6];
    const float* rv     = (const float*)d_in[7];
    float* out          = (float*)d_out;

    int n = in_sizes[0] / D;     // 100000
    int E = in_sizes[1] / 2;     // 1600000

    cudaFuncSetAttribute(gemm_kernel,
                         cudaFuncAttributeMaxDynamicSharedMemorySize, GEMM_SMEM);

    int nprobe = (E < 1024) ? E : 1024;
    setup_kernel<<<(n + 255) / 256, 256>>>(ei32, n, nprobe);
    fill_kernel<<<((E + 3) / 4 + 255) / 256, 256>>>(ei32, E, n);
    gemm_kernel<<<(n + 127) / 128, 256, GEMM_SMEM>>>(x, W, n);
    gather_kernel<<<(n * 32 + 255) / 256, 256>>>(x, b, gamma, beta, rm, rv, out, n);
}

// round 10
// speedup vs baseline: 2.1520x; 1.0847x over previous
#include <cuda_runtime.h>
#include <cuda_fp16.h>
#include <cstdint>

#define NN 100000
#define D 128
#define CAP 192          // per-node in-edge bucket capacity (Poisson(16): P(deg>192) ~ 0)
#define BN_EPS 1e-5f

// Static device scratch (no allocations allowed)
__device__ __half2 g_h2[(size_t)NN * 64];      // (x @ W) * dinv[row], fp16-compressed
__device__ int   g_cnt[NN];                    // in-edge count
__device__ int   g_bucket[(size_t)NN * CAP];   // src node ids grouped by dst
__device__ int   g_is64 = 1;                   // 1 if edge_index is int64, 0 if int32

// ---------------------------------------------------------------------------
// Setup: zero counts + detect edge_index dtype (int64 vs int32).
// ---------------------------------------------------------------------------
__global__ void setup_kernel(const int* __restrict__ ei32, int n, int nprobe) {
    int i = blockIdx.x * blockDim.x + threadIdx.x;
    if (i < n) g_cnt[i] = 0;
    if (i < nprobe) {
        if (ei32[2 * i + 1] != 0) g_is64 = 0;
    }
}

// ---------------------------------------------------------------------------
// Bucket fill: 4 edges per thread, vectorized int4 loads on the int32 path.
// ---------------------------------------------------------------------------
__global__ void fill_kernel(const int* __restrict__ ei32, int E, int n) {
    int t = blockIdx.x * blockDim.x + threadIdx.x;
    int e0 = t * 4;
    if (e0 >= E) return;

    int srcs[4], dsts[4];
    int m = (E - e0 < 4) ? (E - e0) : 4;

    if (!g_is64 && m == 4 && (E & 3) == 0) {
        int4 s4 = *(const int4*)&ei32[e0];
        int4 d4 = *(const int4*)&ei32[(size_t)E + e0];
        srcs[0] = s4.x; srcs[1] = s4.y; srcs[2] = s4.z; srcs[3] = s4.w;
        dsts[0] = d4.x; dsts[1] = d4.y; dsts[2] = d4.z; dsts[3] = d4.w;
    } else {
        #pragma unroll
        for (int j = 0; j < 4; j++) {
            if (j < m) {
                int e = e0 + j;
                if (g_is64) {
                    srcs[j] = ei32[2 * (size_t)e];
                    dsts[j] = ei32[2 * ((size_t)E + e)];
                } else {
                    srcs[j] = ei32[e];
                    dsts[j] = ei32[(size_t)E + e];
                }
            } else { srcs[j] = -1; dsts[j] = -1; }
        }
    }

    #pragma unroll
    for (int j = 0; j < 4; j++) {
        int src = srcs[j], dst = dsts[j];
        if ((unsigned)src >= (unsigned)n) continue;   // trap-safety
        if ((unsigned)dst >= (unsigned)n) continue;
        int slot = atomicAdd(&g_cnt[dst], 1);
        if (slot < CAP) g_bucket[(size_t)dst * CAP + slot] = src;
    }
}

// ---------------------------------------------------------------------------
// tf32 tensor-core GEMM. W staged ONCE to smem as pre-converted tf32
// (no per-chunk B traffic, no B cvts in mainloop). A double-buffered
// via cp.async (fp32 in smem, cvt at fragment load).
// h_s = (x @ W) * rsqrt(cnt+1), output fp16.
// Block tile 128x128, K chunk 32, 256 threads = 8 warps.
// ---------------------------------------------------------------------------
#define WS_WORDS (128 * 136)     // W as tf32, [k][col] stride 136
#define AS_WORDS (128 * 36)      // A chunk, [row][k] stride 36
#define GEMM_SMEM ((WS_WORDS + 2 * AS_WORDS) * 4)

__device__ __forceinline__ unsigned f2tf32(float f) {
    unsigned u;
    asm("cvt.rna.tf32.f32 %0, %1;" : "=r"(u) : "f"(f));
    return u;
}

__device__ __forceinline__ void cp16(float* dst, const float* src) {
    unsigned d = (unsigned)__cvta_generic_to_shared(dst);
    asm volatile("cp.async.cg.shared.global [%0], [%1], 16;" :: "r"(d), "l"(src));
}

__global__ void __launch_bounds__(256) gemm_kernel(const float* __restrict__ x,
                                                   const float* __restrict__ W,
                                                   int n) {
    extern __shared__ float sm[];
    unsigned* Ws = (unsigned*)sm;              // [128][136] tf32
    float* As0 = sm + WS_WORDS;                // stage 0
    float* As1 = As0 + AS_WORDS;               // stage 1

    int tid = threadIdx.x;
    int block_row = blockIdx.x * 128;

    int warp = tid >> 5;
    int lane = tid & 31;
    int group = lane >> 2;      // 0..7
    int tig = lane & 3;         // 0..3
    int warpM = warp & 3;       // 0..3 -> 32-row slab
    int warpN = warp >> 2;      // 0..1 -> 64-col slab

    auto load_chunkA = [&](float* As, int kk) {
        #pragma unroll
        for (int i = tid; i < 1024; i += 256) {   // 128 rows x 8 float4
            int r = i >> 3;
            int c4 = i & 7;
            int gr = block_row + r;
            if (gr >= n) gr = n - 1;              // clamp; ragged rows discarded at store
            cp16(&As[r * 36 + c4 * 4], &x[(size_t)gr * 128 + kk + c4 * 4]);
        }
        asm volatile("cp.async.commit_group;");
    };

    // Prologue: A chunks 0,1 in flight, then stage W (overlaps with cp.async)
    load_chunkA(As0, 0);
    load_chunkA(As1, 32);
    #pragma unroll
    for (int i = tid; i < 128 * 32; i += 256) {   // 128 k-rows x 32 float4
        int r = i >> 5;
        int c4 = i & 31;
        float4 v = ((const float4*)W)[(size_t)r * 32 + c4];
        unsigned* p = &Ws[r * 136 + c4 * 4];
        p[0] = f2tf32(v.x); p[1] = f2tf32(v.y);
        p[2] = f2tf32(v.z); p[3] = f2tf32(v.w);
    }

    float acc[2][8][4];
    #pragma unroll
    for (int t = 0; t < 2; t++)
        #pragma unroll
        for (int u = 0; u < 8; u++)
            #pragma unroll
            for (int v = 0; v < 4; v++) acc[t][u][v] = 0.f;

    #pragma unroll
    for (int c = 0; c < 4; c++) {
        if (c < 3) asm volatile("cp.async.wait_group 1;");
        else       asm volatile("cp.async.wait_group 0;");
        __syncthreads();

        const float* As = (c & 1) ? As1 : As0;
        int kk = c * 32;

        #pragma unroll
        for (int ks = 0; ks < 32; ks += 8) {
            unsigned a[2][4];
            #pragma unroll
            for (int t = 0; t < 2; t++) {
                int rb = warpM * 32 + t * 16;
                a[t][0] = f2tf32(As[(rb + group) * 36 + ks + tig]);
                a[t][1] = f2tf32(As[(rb + group + 8) * 36 + ks + tig]);
                a[t][2] = f2tf32(As[(rb + group) * 36 + ks + tig + 4]);
                a[t][3] = f2tf32(As[(rb + group + 8) * 36 + ks + tig + 4]);
            }
            #pragma unroll
            for (int u = 0; u < 8; u++) {
                int cb = warpN * 64 + u * 8;
                unsigned b0 = Ws[(kk + ks + tig) * 136 + cb + group];
                unsigned b1 = Ws[(kk + ks + tig + 4) * 136 + cb + group];
                #pragma unroll
                for (int t = 0; t < 2; t++) {
                    asm volatile(
                        "mma.sync.aligned.m16n8k8.row.col.f32.tf32.tf32.f32 "
                        "{%0,%1,%2,%3}, {%4,%5,%6,%7}, {%8,%9}, {%0,%1,%2,%3};"
                        : "+f"(acc[t][u][0]), "+f"(acc[t][u][1]),
                          "+f"(acc[t][u][2]), "+f"(acc[t][u][3])
                        : "r"(a[t][0]), "r"(a[t][1]), "r"(a[t][2]), "r"(a[t][3]),
                          "r"(b0), "r"(b1));
                }
            }
        }
        __syncthreads();
        if (c + 2 < 4) load_chunkA((c & 1) ? As1 : As0, (c + 2) * 32);
    }

    // Epilogue: scale by rsqrt(cnt+1), pack fp16, store.
    #pragma unroll
    for (int t = 0; t < 2; t++) {
        int r0 = block_row + warpM * 32 + t * 16 + group;
        int r1 = r0 + 8;
        float d0 = (r0 < n) ? rsqrtf((float)(g_cnt[r0] + 1)) : 0.f;
        float d1 = (r1 < n) ? rsqrtf((float)(g_cnt[r1] + 1)) : 0.f;
        #pragma unroll
        for (int u = 0; u < 8; u++) {
            int colh = (warpN * 64 + u * 8 + 2 * tig) >> 1;
            if (r0 < n)
                g_h2[(size_t)r0 * 64 + colh] =
                    __floats2half2_rn(acc[t][u][0] * d0, acc[t][u][1] * d0);
            if (r1 < n)
                g_h2[(size_t)r1 * 64 + colh] =
                    __floats2half2_rn(acc[t][u][2] * d1, acc[t][u][3] * d1);
        }
    }
}

// ---------------------------------------------------------------------------
// Gather + epilogue: one warp per node, lane handles 4 features (2 half2).
// Strip-mined by 8 edges: 2 int4 bucket loads + 8 h2 loads in flight (MLP=8),
// 3-level HADD2 tree, one cvt+FADD set per group of 8.
// agg = dinv[v] * (h_s[v] + sum_src h_s[src]);  out = relu(BN(agg+b)) + x
// ---------------------------------------------------------------------------
__global__ void gather_kernel(const float* __restrict__ x,
                              const float* __restrict__ b,
                              const float* __restrict__ gamma,
                              const float* __restrict__ beta,
                              const float* __restrict__ rm,
                              const float* __restrict__ rv,
                              float* __restrict__ out,
                              int n) {
    int w = (blockIdx.x * blockDim.x + threadIdx.x) >> 5;   // node id
    int lane = threadIdx.x & 31;
    if (w >= n) return;

    int full = g_cnt[w];
    float dv = rsqrtf((float)(full + 1));
    int cnt = (full > CAP) ? CAP : full;

    const uint2* h2v = (const uint2*)g_h2;      // one uint2 = 4 features

    // self term
    uint2 raw = h2v[(size_t)w * 32 + lane];
    float2 f0 = __half22float2(*(const __half2*)&raw.x);
    float2 f1 = __half22float2(*(const __half2*)&raw.y);
    float ax = f0.x, ay = f0.y, az = f1.x, aw = f1.y;

    const int* bucket = &g_bucket[(size_t)w * CAP];

    int j = 0;
    for (; j + 8 <= cnt; j += 8) {
        int4 sA = *(const int4*)&bucket[j];
        int4 sB = *(const int4*)&bucket[j + 4];
        uint2 t0 = h2v[(size_t)sA.x * 32 + lane];
        uint2 t1 = h2v[(size_t)sA.y * 32 + lane];
        uint2 t2 = h2v[(size_t)sA.z * 32 + lane];
        uint2 t3 = h2v[(size_t)sA.w * 32 + lane];
        uint2 t4 = h2v[(size_t)sB.x * 32 + lane];
        uint2 t5 = h2v[(size_t)sB.y * 32 + lane];
        uint2 t6 = h2v[(size_t)sB.z * 32 + lane];
        uint2 t7 = h2v[(size_t)sB.w * 32 + lane];

        __half2 lo = __hadd2(
            __hadd2(__hadd2(*(const __half2*)&t0.x, *(const __half2*)&t1.x),
                    __hadd2(*(const __half2*)&t2.x, *(const __half2*)&t3.x)),
            __hadd2(__hadd2(*(const __half2*)&t4.x, *(const __half2*)&t5.x),
                    __hadd2(*(const __half2*)&t6.x, *(const __half2*)&t7.x)));
        __half2 hi = __hadd2(
            __hadd2(__hadd2(*(const __half2*)&t0.y, *(const __half2*)&t1.y),
                    __hadd2(*(const __half2*)&t2.y, *(const __half2*)&t3.y)),
            __hadd2(__hadd2(*(const __half2*)&t4.y, *(const __half2*)&t5.y),
                    __hadd2(*(const __half2*)&t6.y, *(const __half2*)&t7.y)));
        float2 lf = __half22float2(lo);
        float2 hf = __half22float2(hi);
        ax += lf.x; ay += lf.y; az += hf.x; aw += hf.y;
    }
    for (; j + 4 <= cnt; j += 4) {
        int4 s4 = *(const int4*)&bucket[j];
        uint2 t0 = h2v[(size_t)s4.x * 32 + lane];
        uint2 t1 = h2v[(size_t)s4.y * 32 + lane];
        uint2 t2 = h2v[(size_t)s4.z * 32 + lane];
        uint2 t3 = h2v[(size_t)s4.w * 32 + lane];
        __half2 lo = __hadd2(__hadd2(*(const __half2*)&t0.x, *(const __half2*)&t1.x),
                             __hadd2(*(const __half2*)&t2.x, *(const __half2*)&t3.x));
        __half2 hi = __hadd2(__hadd2(*(const __half2*)&t0.y, *(const __half2*)&t1.y),
                             __hadd2(*(const __half2*)&t2.y, *(const __half2*)&t3.y));
        float2 lf = __half22float2(lo);
        float2 hf = __half22float2(hi);
        ax += lf.x; ay += lf.y; az += hf.x; aw += hf.y;
    }
    for (; j < cnt; j++) {
        int src = bucket[j];
        uint2 t = h2v[(size_t)src * 32 + lane];
        float2 t0 = __half22float2(*(const __half2*)&t.x);
        float2 t1 = __half22float2(*(const __half2*)&t.y);
        ax += t0.x; ay += t0.y; az += t1.x; aw += t1.y;
    }
    ax *= dv; ay *= dv; az *= dv; aw *= dv;

    // epilogue
    float4 bb = ((const float4*)b)[lane];
    float4 m4 = ((const float4*)rm)[lane];
    float4 v4 = ((const float4*)rv)[lane];
    float4 g4 = ((const float4*)gamma)[lane];
    float4 e4 = ((const float4*)beta)[lane];
    float4 xv = ((const float4*)x)[(size_t)w * 32 + lane];

    float4 o;
    o.x = fmaxf((ax + bb.x - m4.x) * (g4.x * rsqrtf(v4.x + BN_EPS)) + e4.x, 0.f) + xv.x;
    o.y = fmaxf((ay + bb.y - m4.y) * (g4.y * rsqrtf(v4.y + BN_EPS)) + e4.y, 0.f) + xv.y;
    o.z = fmaxf((az + bb.z - m4.z) * (g4.z * rsqrtf(v4.z + BN_EPS)) + e4.z, 0.f) + xv.z;
    o.w = fmaxf((aw + bb.w - m4.w) * (g4.w * rsqrtf(v4.w + BN_EPS)) + e4.w, 0.f) + xv.w;
    ((float4*)out)[(size_t)w * 32 + lane] = o;
}

// ---------------------------------------------------------------------------
extern "C" void kernel_launch(void* const* d_in, const int* in_sizes, int n_in,
                              void* d_out, int out_size) {
    const float* x      = (const float*)d_in[0];
    const int* ei32     = (const int*)d_in[1];     // edge_index (int32; int64 auto-detected)
    const float* W      = (const float*)d_in[2];
    const float* b      = (const float*)d_in[3];
    const float* gamma  = (const float*)d_in[4];
    const float* beta   = (const float*)d_in[5];
    const float* rm     = (const float*)d_in[6];
    const float* rv     = (const float*)d_in[7];
    float* out          = (float*)d_out;

    int n = in_sizes[0] / D;     // 100000
    int E = in_sizes[1] / 2;     // 1600000

    cudaFuncSetAttribute(gemm_kernel,
                         cudaFuncAttributeMaxDynamicSharedMemorySize, GEMM_SMEM);

    int nprobe = (E < 1024) ? E : 1024;
    setup_kernel<<<(n + 255) / 256, 256>>>(ei32, n, nprobe);
    fill_kernel<<<((E + 3) / 4 + 255) / 256, 256>>>(ei32, E, n);
    gemm_kernel<<<(n + 127) / 128, 256, GEMM_SMEM>>>(x, W, n);
    gather_kernel<<<(n * 32 + 255) / 256, 256>>>(x, b, gamma, beta, rm, rv, out, n);
}